// round 4
// baseline (speedup 1.0000x reference)
#include <cuda_runtime.h>
#include <cuda_bf16.h>
#include <math.h>

#define D  1024
#define T  2048
#define V  32000
#define NB 64      // persistent CTAs (must all be co-resident; 64 << 148 SMs)
#define JT 16      // hidden units owned per persistent CTA (NB*JT == D)

// ---------------- device scratch (no allocs allowed) ----------------
__device__ float g_xpre[(size_t)T * 4 * D];   // 32 MB: per-step per-gate x-contribution + bias
__device__ float g_h[2][D];                   // double-buffered hidden state
__device__ unsigned int g_bar_count;
__device__ unsigned int g_bar_sense;

// ---------------- kernel 1: gather x-projections, reset state ----------------
__global__ void __launch_bounds__(256) gather_kernel(
    const int* __restrict__ X32,
    const float* __restrict__ Wxf, const float* __restrict__ Wxi,
    const float* __restrict__ Wxc, const float* __restrict__ Wxo,
    const float* __restrict__ bf,  const float* __restrict__ bi,
    const float* __restrict__ bc,  const float* __restrict__ bo)
{
    int t   = blockIdx.x;
    int tid = threadIdx.x;

    // Detect int64-vs-int32 ids: little-endian int64 ids < 32000 -> all odd
    // 32-bit words are zero. Sample 64 odd words (in-bounds for either dtype).
    int pred = 0;
    if (tid < 64) {
        int p = (tid * 37) & 1023;          // p in [0,1024) -> index 2p+1 <= 2047
        pred = (X32[2 * p + 1] != 0);
    }
    int any_nonzero = __syncthreads_or(pred);
    int id = any_nonzero ? X32[t] : X32[2 * t];   // int32 : int64(low word)

    if (t == 0) {
        if (tid == 0) { g_bar_count = 0u; g_bar_sense = 0u; }
        ((float4*)g_h[0])[tid] = make_float4(0.f, 0.f, 0.f, 0.f);  // 256*4 = 1024
    }

    const float* Wx[4] = {Wxf, Wxi, Wxc, Wxo};
    const float* bs[4] = {bf,  bi,  bc,  bo};
    size_t rowoff = (size_t)id * D;
    int j = tid * 4;                         // 256 threads * float4 = 1024 = D
    #pragma unroll
    for (int g = 0; g < 4; ++g) {
        float4 v = *(const float4*)(Wx[g] + rowoff + j);
        float4 b = *(const float4*)(bs[g] + j);
        v.x += b.x; v.y += b.y; v.z += b.z; v.w += b.w;
        *(float4*)(g_xpre + ((size_t)t * 4 + g) * D + j) = v;
    }
}

// ---------------- kernel 2: persistent sequential LSTM ----------------
// 64 CTAs x 256 threads. CTA b owns hidden indices [16b, 16b+16) and keeps
// their cell state in SMEM. Per step: each thread computes a float4 partial
// dot (one gate, one 64-long K-chunk, 4 consecutive j), SMEM tree-reduce,
// activation + state update, publish h, global sense barrier.
__global__ void __launch_bounds__(256, 1) lstm_kernel(
    const float* __restrict__ Whf, const float* __restrict__ Whi,
    const float* __restrict__ Whc, const float* __restrict__ Who,
    float* __restrict__ hid_out)
{
    __shared__ float sh_h[D];
    __shared__ float sh_ps[4 * 16 * JT];   // [gate][kchunk][jx]
    __shared__ float sh_act[4 * JT];
    __shared__ float sh_c[JT];

    int tid   = threadIdx.x;
    int jbase = blockIdx.x * JT;
    int jv = tid & 3;          // which float4 within the 16-wide j tile
    int r  = tid >> 2;
    int g  = r & 3;            // gate: 0=f 1=i 2=c 3=o
    int kc = r >> 2;           // K-chunk 0..15, each 64 i's

    const float* whsel = (g == 0) ? Whf : (g == 1) ? Whi : (g == 2) ? Whc : Who;
    const float* wbase = whsel + (size_t)(kc * 64) * D + jbase + jv * 4;

    if (tid < JT) sh_c[tid] = 0.f;

    for (int t = 0; t < T; ++t) {
        // load h_{t-1} (written by other SMs -> must bypass L1)
        float4 hv = __ldcg(((const float4*)g_h[t & 1]) + tid);
        ((float4*)sh_h)[tid] = hv;
        __syncthreads();

        float4 acc = make_float4(0.f, 0.f, 0.f, 0.f);
        const float* hp = sh_h + kc * 64;
        const float* wp = wbase;
        #pragma unroll 8
        for (int ii = 0; ii < 64; ++ii) {
            float h  = hp[ii];
            float4 w = *(const float4*)wp;     // L2-resident after first step
            acc.x = fmaf(h, w.x, acc.x);
            acc.y = fmaf(h, w.y, acc.y);
            acc.z = fmaf(h, w.z, acc.z);
            acc.w = fmaf(h, w.w, acc.w);
            wp += D;
        }
        float* ps = sh_ps + (g * 16 + kc) * JT + jv * 4;
        ps[0] = acc.x; ps[1] = acc.y; ps[2] = acc.z; ps[3] = acc.w;
        __syncthreads();

        if (tid < 64) {
            int gg = tid >> 4, jx = tid & 15;
            float s = 0.f;
            #pragma unroll
            for (int k2 = 0; k2 < 16; ++k2)
                s += sh_ps[(gg * 16 + k2) * JT + jx];
            s += g_xpre[((size_t)t * 4 + gg) * D + jbase + jx];
            sh_act[gg * JT + jx] = (gg == 2) ? tanhf(s)
                                             : 1.f / (1.f + expf(-s));
        }
        __syncthreads();

        if (tid < JT) {
            float f  = sh_act[tid];
            float in = sh_act[JT + tid];
            float gv = sh_act[2 * JT + tid];
            float o  = sh_act[3 * JT + tid];
            float c  = fmaf(f, sh_c[tid], in * gv);
            sh_c[tid] = c;
            float h = tanhf(c) * o;
            __stcg(&g_h[(t + 1) & 1][jbase + tid], h);   // next step's input
            hid_out[(size_t)t * D + jbase + tid] = h;    // output tensor
            __threadfence();                             // push before barrier
        }

        // grid-wide sense barrier (all NB CTAs co-resident by construction)
        __syncthreads();
        if (tid == 0) {
            unsigned target = (unsigned)(t + 1);
            unsigned tk = atomicAdd(&g_bar_count, 1u);
            if (tk == NB - 1) {
                g_bar_count = 0u;
                __threadfence();
                atomicExch(&g_bar_sense, target);
            } else {
                volatile unsigned* vs = &g_bar_sense;
                while (*vs < target) { }
                __threadfence();
            }
        }
        __syncthreads();
    }
}

// ---------------- kernel 3: logits GEMM  C = H @ W^T + bias ----------------
// 128x128 block tile, BK=16, 8x8 microtile per thread, fp32.
__global__ void __launch_bounds__(256) gemm_kernel(
    const float* __restrict__ H,      // (T, D)
    const float* __restrict__ W,      // (V, D)
    const float* __restrict__ bias,   // (V)
    float* __restrict__ out)          // (T, V)
{
    __shared__ float Hs[16][132];
    __shared__ float Ws[16][132];
    int tid = threadIdx.x;
    int tx = tid & 15;
    int ty = tid >> 4;
    int t0 = blockIdx.y * 128;
    int v0 = blockIdx.x * 128;

    float acc[8][8];
    #pragma unroll
    for (int i = 0; i < 8; ++i)
        #pragma unroll
        for (int j = 0; j < 8; ++j) acc[i][j] = 0.f;

    for (int d0 = 0; d0 < D; d0 += 16) {
        #pragma unroll
        for (int s = 0; s < 2; ++s) {
            int f   = tid + s * 256;
            int row = f >> 2;
            int kq  = (f & 3) * 4;
            float4 hv = *(const float4*)(H + (size_t)(t0 + row) * D + d0 + kq);
            Hs[kq + 0][row] = hv.x; Hs[kq + 1][row] = hv.y;
            Hs[kq + 2][row] = hv.z; Hs[kq + 3][row] = hv.w;
            float4 wv = *(const float4*)(W + (size_t)(v0 + row) * D + d0 + kq);
            Ws[kq + 0][row] = wv.x; Ws[kq + 1][row] = wv.y;
            Ws[kq + 2][row] = wv.z; Ws[kq + 3][row] = wv.w;
        }
        __syncthreads();
        #pragma unroll
        for (int k = 0; k < 16; ++k) {
            float a[8], b[8];
            *(float4*)&a[0] = *(const float4*)&Hs[k][ty * 8];
            *(float4*)&a[4] = *(const float4*)&Hs[k][ty * 8 + 4];
            *(float4*)&b[0] = *(const float4*)&Ws[k][tx * 8];
            *(float4*)&b[4] = *(const float4*)&Ws[k][tx * 8 + 4];
            #pragma unroll
            for (int i = 0; i < 8; ++i)
                #pragma unroll
                for (int j = 0; j < 8; ++j)
                    acc[i][j] = fmaf(a[i], b[j], acc[i][j]);
        }
        __syncthreads();
    }

    #pragma unroll
    for (int i = 0; i < 8; ++i) {
        size_t trow = (size_t)(t0 + ty * 8 + i) * V;
        #pragma unroll
        for (int j = 0; j < 8; j += 4) {
            int v = v0 + tx * 8 + j;
            float4 o;
            o.x = acc[i][j + 0] + bias[v + 0];
            o.y = acc[i][j + 1] + bias[v + 1];
            o.z = acc[i][j + 2] + bias[v + 2];
            o.w = acc[i][j + 3] + bias[v + 3];
            *(float4*)(out + trow + v) = o;
        }
    }
}

// ---------------- kernel 4: in-place log_softmax over V ----------------
__global__ void __launch_bounds__(256) logsoftmax_kernel(float* __restrict__ out)
{
    size_t t  = blockIdx.x;
    float* row = out + t * (size_t)V;
    int tid = threadIdx.x;
    __shared__ float red[8];

    float m = -INFINITY;
    for (int v = tid; v < V; v += 256) m = fmaxf(m, row[v]);
    #pragma unroll
    for (int o = 16; o; o >>= 1) m = fmaxf(m, __shfl_xor_sync(0xffffffffu, m, o));
    if ((tid & 31) == 0) red[tid >> 5] = m;
    __syncthreads();
    float rm = red[0];
    #pragma unroll
    for (int i = 1; i < 8; ++i) rm = fmaxf(rm, red[i]);
    __syncthreads();

    float s = 0.f;
    for (int v = tid; v < V; v += 256) s += expf(row[v] - rm);
    #pragma unroll
    for (int o = 16; o; o >>= 1) s += __shfl_xor_sync(0xffffffffu, s, o);
    if ((tid & 31) == 0) red[tid >> 5] = s;
    __syncthreads();
    float rs = 0.f;
    #pragma unroll
    for (int i = 0; i < 8; ++i) rs += red[i];

    float lse = rm + logf(rs);
    for (int v = tid; v < V; v += 256) row[v] -= lse;
}

// ---------------- launch ----------------
extern "C" void kernel_launch(void* const* d_in, const int* in_sizes, int n_in,
                              void* d_out, int out_size)
{
    const int*   X   = (const int*)d_in[0];
    const float* Wxf = (const float*)d_in[1];
    const float* Whf = (const float*)d_in[2];
    const float* Wxi = (const float*)d_in[3];
    const float* Whi = (const float*)d_in[4];
    const float* Wxc = (const float*)d_in[5];
    const float* Whc = (const float*)d_in[6];
    const float* Wxo = (const float*)d_in[7];
    const float* Who = (const float*)d_in[8];
    const float* LW  = (const float*)d_in[9];
    const float* bf  = (const float*)d_in[10];
    const float* bi  = (const float*)d_in[11];
    const float* bc  = (const float*)d_in[12];
    const float* bo  = (const float*)d_in[13];
    const float* LB  = (const float*)d_in[14];

    float* out = (float*)d_out;                     // (T, V) log-softmax
    float* hid = out + (size_t)T * V;               // (1, T, D) hidden states

    gather_kernel<<<T, 256>>>(X, Wxf, Wxi, Wxc, Wxo, bf, bi, bc, bo);
    lstm_kernel<<<NB, 256>>>(Whf, Whi, Whc, Who, hid);
    dim3 gg(V / 128, T / 128);
    gemm_kernel<<<gg, 256>>>(hid, LW, LB, out);
    logsoftmax_kernel<<<T, 256>>>(out);
}

// round 6
// speedup vs baseline: 1.2474x; 1.2474x over previous
#include <cuda_runtime.h>
#include <cuda_bf16.h>
#include <cstdint>
#include <math.h>

#define D  1024
#define T  2048
#define V  32000
#define NB 64      // persistent CTAs (must all be co-resident; 64 << 148 SMs)
#define JT 16      // hidden units owned per persistent CTA (NB*JT == D)

// ---------------- device scratch (no allocs allowed) ----------------
__device__ float g_xpre[(size_t)T * 4 * D];        // 32 MB x-contribution + bias
__device__ float g_h[2][D];                        // double-buffered hidden state
__device__ __nv_bfloat16 g_Hbf[(size_t)T * D];     // 4 MB  bf16 hidden states
__device__ __nv_bfloat16 g_Wbf[(size_t)V * D];     // 64 MB bf16 linear weight
__device__ unsigned int g_bar_count;
__device__ unsigned int g_bar_sense;

// ---------------- kernel 1: gather x-projections, reset state ----------------
__global__ void __launch_bounds__(256) gather_kernel(
    const int* __restrict__ X32,
    const float* __restrict__ Wxf, const float* __restrict__ Wxi,
    const float* __restrict__ Wxc, const float* __restrict__ Wxo,
    const float* __restrict__ bf,  const float* __restrict__ bi,
    const float* __restrict__ bc,  const float* __restrict__ bo)
{
    int t   = blockIdx.x;
    int tid = threadIdx.x;

    // int64 vs int32 ids: little-endian int64 ids < 32000 -> odd words zero.
    int pred = 0;
    if (tid < 64) {
        int p = (tid * 37) & 1023;
        pred = (X32[2 * p + 1] != 0);
    }
    int any_nonzero = __syncthreads_or(pred);
    int id = any_nonzero ? X32[t] : X32[2 * t];

    if (t == 0) {
        if (tid == 0) { g_bar_count = 0u; g_bar_sense = 0u; }
        ((float4*)g_h[0])[tid] = make_float4(0.f, 0.f, 0.f, 0.f);
    }

    const float* Wx[4] = {Wxf, Wxi, Wxc, Wxo};
    const float* bs[4] = {bf,  bi,  bc,  bo};
    size_t rowoff = (size_t)id * D;
    int j = tid * 4;
    #pragma unroll
    for (int g = 0; g < 4; ++g) {
        float4 v = *(const float4*)(Wx[g] + rowoff + j);
        float4 b = *(const float4*)(bs[g] + j);
        v.x += b.x; v.y += b.y; v.z += b.z; v.w += b.w;
        *(float4*)(g_xpre + ((size_t)t * 4 + g) * D + j) = v;
    }
}

// ---------------- kernel 1b: convert linear_weight to bf16 ----------------
__global__ void __launch_bounds__(256) cvt_kernel(const float* __restrict__ W)
{
    size_t i = (size_t)blockIdx.x * 256 + threadIdx.x;   // float4 index
    float4 v = ((const float4*)W)[i];
    __nv_bfloat162* o = (__nv_bfloat162*)g_Wbf + i * 2;
    o[0] = __floats2bfloat162_rn(v.x, v.y);
    o[1] = __floats2bfloat162_rn(v.z, v.w);
}

// ---------------- kernel 2: persistent sequential LSTM ----------------
__global__ void __launch_bounds__(256, 1) lstm_kernel(
    const float* __restrict__ Whf, const float* __restrict__ Whi,
    const float* __restrict__ Whc, const float* __restrict__ Who,
    float* __restrict__ hid_out)
{
    __shared__ float sh_h[D];
    __shared__ float sh_ps[4 * 16 * JT];
    __shared__ float sh_act[4 * JT];
    __shared__ float sh_c[JT];

    int tid   = threadIdx.x;
    int jbase = blockIdx.x * JT;
    int jv = tid & 3;
    int r  = tid >> 2;
    int g  = r & 3;
    int kc = r >> 2;

    const float* whsel = (g == 0) ? Whf : (g == 1) ? Whi : (g == 2) ? Whc : Who;
    const float* wbase = whsel + (size_t)(kc * 64) * D + jbase + jv * 4;

    if (tid < JT) sh_c[tid] = 0.f;

    for (int t = 0; t < T; ++t) {
        float4 hv = __ldcg(((const float4*)g_h[t & 1]) + tid);
        ((float4*)sh_h)[tid] = hv;

        // prefetch x-contribution early (latency hidden behind dot products)
        float xv = 0.f;
        if (tid < 64)
            xv = g_xpre[((size_t)t * 4 + (tid >> 4)) * D + jbase + (tid & 15)];
        __syncthreads();

        float4 acc = make_float4(0.f, 0.f, 0.f, 0.f);
        const float* hp = sh_h + kc * 64;
        const float* wp = wbase;
        #pragma unroll 8
        for (int ii = 0; ii < 64; ++ii) {
            float h  = hp[ii];
            float4 w = *(const float4*)wp;
            acc.x = fmaf(h, w.x, acc.x);
            acc.y = fmaf(h, w.y, acc.y);
            acc.z = fmaf(h, w.z, acc.z);
            acc.w = fmaf(h, w.w, acc.w);
            wp += D;
        }
        float* ps = sh_ps + (g * 16 + kc) * JT + jv * 4;
        ps[0] = acc.x; ps[1] = acc.y; ps[2] = acc.z; ps[3] = acc.w;
        __syncthreads();

        if (tid < 64) {
            int gg = tid >> 4, jx = tid & 15;
            float s = xv;
            #pragma unroll
            for (int k2 = 0; k2 < 16; ++k2)
                s += sh_ps[(gg * 16 + k2) * JT + jx];
            sh_act[gg * JT + jx] = (gg == 2) ? tanhf(s)
                                             : 1.f / (1.f + expf(-s));
        }
        __syncthreads();

        if (tid < JT) {
            float f  = sh_act[tid];
            float in = sh_act[JT + tid];
            float gv = sh_act[2 * JT + tid];
            float o  = sh_act[3 * JT + tid];
            float c  = fmaf(f, sh_c[tid], in * gv);
            sh_c[tid] = c;
            float h = tanhf(c) * o;
            __stcg(&g_h[(t + 1) & 1][jbase + tid], h);
            hid_out[(size_t)t * D + jbase + tid] = h;
            g_Hbf[(size_t)t * D + jbase + tid] = __float2bfloat16(h);
            __threadfence();
        }

        __syncthreads();
        if (tid == 0) {
            unsigned target = (unsigned)(t + 1);
            unsigned tk = atomicAdd(&g_bar_count, 1u);
            if (tk == NB - 1) {
                g_bar_count = 0u;
                __threadfence();
                atomicExch(&g_bar_sense, target);
            } else {
                volatile unsigned* vs = &g_bar_sense;
                while (*vs < target) { }
                __threadfence();
            }
        }
        __syncthreads();
    }
}

// ---------------- kernel 3: bf16 tensor-core GEMM  C = H @ W^T + bias ----------
// 128x128 block tile, BK=32, 8 warps (2x4), 64x32 warp tile, mma.m16n8k16.bf16.
__global__ void __launch_bounds__(256) gemm_kernel(
    const float* __restrict__ bias,   // (V)
    float* __restrict__ out)          // (T, V)
{
    __shared__ __align__(16) __nv_bfloat16 As[2][128][40];
    __shared__ __align__(16) __nv_bfloat16 Bs[2][128][40];

    int tid  = threadIdx.x;
    int lane = tid & 31;
    int w    = tid >> 5;
    int wm   = w >> 2;          // 0..1 -> m offset 64*wm
    int wn   = w & 3;           // 0..3 -> n offset 32*wn
    int t0   = blockIdx.y * 128;
    int v0   = blockIdx.x * 128;

    const __nv_bfloat16* Hbf = g_Hbf;
    const __nv_bfloat16* Wbf = g_Wbf;

    float acc[4][4][4];
    #pragma unroll
    for (int mi = 0; mi < 4; ++mi)
        #pragma unroll
        for (int ni = 0; ni < 4; ++ni)
            #pragma unroll
            for (int q = 0; q < 4; ++q) acc[mi][ni][q] = 0.f;

    // initial tile (kb = 0)
    #pragma unroll
    for (int s = 0; s < 2; ++s) {
        int f = tid + s * 256, row = f >> 2, q = f & 3;
        *(uint4*)&As[0][row][q * 8] =
            *(const uint4*)(Hbf + (size_t)(t0 + row) * D + q * 8);
        *(uint4*)&Bs[0][row][q * 8] =
            *(const uint4*)(Wbf + (size_t)(v0 + row) * D + q * 8);
    }
    __syncthreads();

    int p = 0;
    for (int kb = 0; kb < 32; ++kb) {
        uint4 ra[2], rb[2];
        if (kb < 31) {
            int d0 = (kb + 1) * 32;
            #pragma unroll
            for (int s = 0; s < 2; ++s) {
                int f = tid + s * 256, row = f >> 2, q = f & 3;
                ra[s] = *(const uint4*)(Hbf + (size_t)(t0 + row) * D + d0 + q * 8);
                rb[s] = *(const uint4*)(Wbf + (size_t)(v0 + row) * D + d0 + q * 8);
            }
        }

        #pragma unroll
        for (int ks = 0; ks < 2; ++ks) {
            int k0 = ks * 16;
            uint32_t af[4][4];
            #pragma unroll
            for (int mi = 0; mi < 4; ++mi) {
                int row = wm * 64 + mi * 16 + (lane & 7) + ((lane >> 3) & 1) * 8;
                int kc  = k0 + (lane >> 4) * 8;
                uint32_t a = (uint32_t)__cvta_generic_to_shared(&As[p][row][kc]);
                asm volatile(
                    "ldmatrix.sync.aligned.m8n8.x4.shared.b16 {%0,%1,%2,%3}, [%4];"
                    : "=r"(af[mi][0]), "=r"(af[mi][1]),
                      "=r"(af[mi][2]), "=r"(af[mi][3]) : "r"(a));
            }
            uint32_t bfr[4][2];
            #pragma unroll
            for (int ni = 0; ni < 4; ++ni) {
                int nrow = wn * 32 + ni * 8 + (lane & 7);
                int kc   = k0 + ((lane >> 3) & 1) * 8;
                uint32_t a = (uint32_t)__cvta_generic_to_shared(&Bs[p][nrow][kc]);
                asm volatile(
                    "ldmatrix.sync.aligned.m8n8.x2.shared.b16 {%0,%1}, [%2];"
                    : "=r"(bfr[ni][0]), "=r"(bfr[ni][1]) : "r"(a));
            }
            #pragma unroll
            for (int mi = 0; mi < 4; ++mi)
                #pragma unroll
                for (int ni = 0; ni < 4; ++ni)
                    asm volatile(
                        "mma.sync.aligned.m16n8k16.row.col.f32.bf16.bf16.f32 "
                        "{%0,%1,%2,%3}, {%4,%5,%6,%7}, {%8,%9}, {%0,%1,%2,%3};"
                        : "+f"(acc[mi][ni][0]), "+f"(acc[mi][ni][1]),
                          "+f"(acc[mi][ni][2]), "+f"(acc[mi][ni][3])
                        : "r"(af[mi][0]), "r"(af[mi][1]),
                          "r"(af[mi][2]), "r"(af[mi][3]),
                          "r"(bfr[ni][0]), "r"(bfr[ni][1]));
        }

        if (kb < 31) {
            #pragma unroll
            for (int s = 0; s < 2; ++s) {
                int f = tid + s * 256, row = f >> 2, q = f & 3;
                *(uint4*)&As[p ^ 1][row][q * 8] = ra[s];
                *(uint4*)&Bs[p ^ 1][row][q * 8] = rb[s];
            }
        }
        __syncthreads();
        p ^= 1;
    }

    // epilogue: add bias, write fp32
    int rowA = lane >> 2;
    int colB = (lane & 3) * 2;
    #pragma unroll
    for (int mi = 0; mi < 4; ++mi) {
        int m = t0 + wm * 64 + mi * 16 + rowA;
        #pragma unroll
        for (int ni = 0; ni < 4; ++ni) {
            int n = v0 + wn * 32 + ni * 8 + colB;
            float bx = bias[n], by = bias[n + 1];
            *(float2*)(out + (size_t)m * V + n) =
                make_float2(acc[mi][ni][0] + bx, acc[mi][ni][1] + by);
            *(float2*)(out + (size_t)(m + 8) * V + n) =
                make_float2(acc[mi][ni][2] + bx, acc[mi][ni][3] + by);
        }
    }
}

// ---------------- kernel 4: online single-read log_softmax ----------------
__global__ void __launch_bounds__(256) logsoftmax_kernel(float* __restrict__ out)
{
    size_t t   = blockIdx.x;
    float* row = out + t * (size_t)V;
    int tid = threadIdx.x;
    __shared__ float sm[8], ss[8];

    float m = -INFINITY, s = 0.f;
    const float4* r4 = (const float4*)row;
    for (int i = tid; i < V / 4; i += 256) {
        float4 v = r4[i];
        float mx = fmaxf(fmaxf(v.x, v.y), fmaxf(v.z, v.w));
        if (mx > m) { s *= expf(m - mx); m = mx; }
        s += expf(v.x - m) + expf(v.y - m) + expf(v.z - m) + expf(v.w - m);
    }
    #pragma unroll
    for (int o = 16; o; o >>= 1) {
        float mo = __shfl_xor_sync(0xffffffffu, m, o);
        float so = __shfl_xor_sync(0xffffffffu, s, o);
        float mn = fmaxf(m, mo);
        s = s * expf(m - mn) + so * expf(mo - mn);
        m = mn;
    }
    if ((tid & 31) == 0) { sm[tid >> 5] = m; ss[tid >> 5] = s; }
    __syncthreads();
    float M = sm[0], S = ss[0];
    #pragma unroll
    for (int i = 1; i < 8; ++i) {
        float mo = sm[i], so = ss[i];
        float mn = fmaxf(M, mo);
        S = S * expf(M - mn) + so * expf(mo - mn);
        M = mn;
    }
    float lse = M + logf(S);
    for (int i = tid; i < V / 4; i += 256) {
        float4 v = r4[i];
        v.x -= lse; v.y -= lse; v.z -= lse; v.w -= lse;
        ((float4*)row)[i] = v;
    }
}

// ---------------- launch ----------------
extern "C" void kernel_launch(void* const* d_in, const int* in_sizes, int n_in,
                              void* d_out, int out_size)
{
    const int*   X   = (const int*)d_in[0];
    const float* Wxf = (const float*)d_in[1];
    const float* Whf = (const float*)d_in[2];
    const float* Wxi = (const float*)d_in[3];
    const float* Whi = (const float*)d_in[4];
    const float* Wxc = (const float*)d_in[5];
    const float* Whc = (const float*)d_in[6];
    const float* Wxo = (const float*)d_in[7];
    const float* Who = (const float*)d_in[8];
    const float* LW  = (const float*)d_in[9];
    const float* bf  = (const float*)d_in[10];
    const float* bi  = (const float*)d_in[11];
    const float* bc  = (const float*)d_in[12];
    const float* bo  = (const float*)d_in[13];
    const float* LB  = (const float*)d_in[14];

    float* out = (float*)d_out;                     // (T, V) log-softmax
    float* hid = out + (size_t)T * V;               // (1, T, D) hidden states

    gather_kernel<<<T, 256>>>(X, Wxf, Wxi, Wxc, Wxo, bf, bi, bc, bo);
    cvt_kernel<<<(int)(((size_t)V * D / 4) / 256), 256>>>(LW);
    lstm_kernel<<<NB, 256>>>(Whf, Whi, Whc, Who, hid);
    dim3 gg(V / 128, T / 128);
    gemm_kernel<<<gg, 256>>>(LB, out);
    logsoftmax_kernel<<<T, 256>>>(out);
}

// round 8
// speedup vs baseline: 1.6400x; 1.3147x over previous
#include <cuda_runtime.h>
#include <cuda_bf16.h>
#include <cstdint>
#include <math.h>

#define D  1024
#define T  2048
#define V  32000
#define NB 128     // persistent CTAs, 1 per SM (128 <= 148)
#define JT 8       // hidden units owned per CTA (NB*JT == D)

// ---------------- device scratch (no allocs allowed) ----------------
__device__ __align__(16) float g_xpre[(size_t)T * 4 * D];    // 32 MB x-contrib + bias
__device__ __align__(16) float g_h[2][D];                    // double-buffered hidden
__device__ __align__(16) __nv_bfloat16 g_Hbf[(size_t)T * D]; // 4 MB bf16 hidden states
__device__ __align__(16) __nv_bfloat16 g_Wbf[(size_t)V * D]; // 64 MB bf16 linear weight
__device__ __align__(16) unsigned int g_flags[NB];           // per-CTA step flags

// ---------------- kernel 1: gather x-projections, reset state ----------------
__global__ void __launch_bounds__(256) gather_kernel(
    const int* __restrict__ X32,
    const float* __restrict__ Wxf, const float* __restrict__ Wxi,
    const float* __restrict__ Wxc, const float* __restrict__ Wxo,
    const float* __restrict__ bf,  const float* __restrict__ bi,
    const float* __restrict__ bc,  const float* __restrict__ bo)
{
    int t   = blockIdx.x;
    int tid = threadIdx.x;

    // int64 vs int32 ids: little-endian int64 ids < 32000 -> odd words zero.
    int pred = 0;
    if (tid < 64) {
        int p = (tid * 37) & 1023;
        pred = (X32[2 * p + 1] != 0);
    }
    int any_nonzero = __syncthreads_or(pred);
    int id = any_nonzero ? X32[t] : X32[2 * t];

    if (t == 0) {
        if (tid < NB) g_flags[tid] = 0u;
        ((float4*)g_h[0])[tid] = make_float4(0.f, 0.f, 0.f, 0.f);
    }

    const float* Wx[4] = {Wxf, Wxi, Wxc, Wxo};
    const float* bs[4] = {bf,  bi,  bc,  bo};
    size_t rowoff = (size_t)id * D;
    int j = tid * 4;
    #pragma unroll
    for (int g = 0; g < 4; ++g) {
        float4 v = *(const float4*)(Wx[g] + rowoff + j);
        float4 b = *(const float4*)(bs[g] + j);
        v.x += b.x; v.y += b.y; v.z += b.z; v.w += b.w;
        *(float4*)(g_xpre + ((size_t)t * 4 + g) * D + j) = v;
    }
}

// ---------------- kernel 1b: convert linear_weight to bf16 ----------------
__global__ void __launch_bounds__(256) cvt_kernel(const float* __restrict__ W)
{
    size_t i = (size_t)blockIdx.x * 256 + threadIdx.x;   // float4 index
    float4 v = ((const float4*)W)[i];
    __nv_bfloat162* o = (__nv_bfloat162*)g_Wbf + i * 2;
    o[0] = __floats2bfloat162_rn(v.x, v.y);
    o[1] = __floats2bfloat162_rn(v.z, v.w);
}

// ---------------- kernel 2: persistent LSTM, weights in registers ----------
// 128 CTAs x 256 threads, 1 CTA/SM. Thread (warp w, lane) holds
// W[gate(lane>>3)][k in 128w..128w+128)][j = 8*cta + (lane&7)] in 128 regs.
// Per step: 128 reg-FMAs vs SMEM-broadcast h, SMEM cross-warp reduce, warp 0
// does activations + state update + publishes h + flag (atomicExch), warp 1
// polls all flags with volatile scalar loads (non-hoistable).
__global__ void __launch_bounds__(256, 1) lstm_kernel(
    const float* __restrict__ Whf, const float* __restrict__ Whi,
    const float* __restrict__ Whc, const float* __restrict__ Who,
    float* __restrict__ hid_out)
{
    __shared__ float sh_h[D];
    __shared__ float sh_ps[8][33];

    int tid   = threadIdx.x;
    int w     = tid >> 5;
    int lane  = tid & 31;
    int g     = lane >> 3;
    int jj    = lane & 7;
    int jbase = blockIdx.x * JT;
    int j     = jbase + jj;

    const float* Wm = (g == 0) ? Whf : (g == 1) ? Whi : (g == 2) ? Whc : Who;
    float wreg[128];
    #pragma unroll
    for (int kk = 0; kk < 128; ++kk)
        wreg[kk] = Wm[(size_t)(w * 128 + kk) * D + j];

    // h0 (zeroed by gather_kernel)
    ((float4*)sh_h)[tid] = __ldcg(((const float4*)g_h[0]) + tid);
    float c = 0.f;   // cell state: lives in warp-0 lanes 0..7
    __syncthreads();

    for (int t = 0; t < T; ++t) {
        unsigned target = (unsigned)(t + 1);

        float xv = 0.f;
        if (w == 0) xv = __ldcs(&g_xpre[((size_t)t * 4 + g) * D + j]);

        float acc = 0.f;
        const float4* h4 = ((const float4*)sh_h) + w * 32;
        #pragma unroll
        for (int q = 0; q < 32; ++q) {
            float4 hv = h4[q];
            acc = fmaf(hv.x, wreg[4 * q + 0], acc);
            acc = fmaf(hv.y, wreg[4 * q + 1], acc);
            acc = fmaf(hv.z, wreg[4 * q + 2], acc);
            acc = fmaf(hv.w, wreg[4 * q + 3], acc);
        }
        sh_ps[w][lane] = acc;
        __syncthreads();

        if (w == 0) {
            float s = xv;
            #pragma unroll
            for (int q = 0; q < 8; ++q) s += sh_ps[q][lane];
            float a = (g == 2) ? tanhf(s) : 1.f / (1.f + expf(-s));
            float fv = __shfl_sync(0xffffffffu, a, jj);
            float iv = __shfl_sync(0xffffffffu, a, 8 + jj);
            float gv = __shfl_sync(0xffffffffu, a, 16 + jj);
            float ov = __shfl_sync(0xffffffffu, a, 24 + jj);
            if (lane < 8) {
                c = fmaf(fv, c, iv * gv);
                float h = tanhf(c) * ov;
                __stcg(&g_h[target & 1][jbase + lane], h);
                hid_out[(size_t)t * D + jbase + lane] = h;
                g_Hbf[(size_t)t * D + jbase + lane] = __float2bfloat16(h);
            }
            __threadfence();      // h visible before flag (release)
            __syncwarp();
            if (lane == 0) atomicExch(&g_flags[blockIdx.x], target);
        } else if (w == 1) {
            // poll all NB flags: lane reads 4 flags via VOLATILE scalar loads
            // (ld.volatile.global — ptxas cannot hoist these out of the loop)
            const volatile unsigned* fp =
                (const volatile unsigned*)(g_flags) + lane * 4;
            for (;;) {
                unsigned f0 = fp[0], f1 = fp[1], f2 = fp[2], f3 = fp[3];
                unsigned mn = min(min(f0, f1), min(f2, f3));
                if (__all_sync(0xffffffffu, mn >= target)) break;
            }
            __threadfence();      // acquire before reading peers' h
        }
        __syncthreads();

        // load h_{t+1}
        ((float4*)sh_h)[tid] = __ldcg(((const float4*)g_h[target & 1]) + tid);
        __syncthreads();
    }
}

// ---------------- kernel 3: bf16 tensor-core GEMM  C = H @ W^T + bias ----------
// 128x128 block tile, BK=32, 8 warps (2x4), 64x32 warp tile, mma.m16n8k16.bf16.
__global__ void __launch_bounds__(256) gemm_kernel(
    const float* __restrict__ bias,   // (V)
    float* __restrict__ out)          // (T, V)
{
    __shared__ __align__(16) __nv_bfloat16 As[2][128][40];
    __shared__ __align__(16) __nv_bfloat16 Bs[2][128][40];

    int tid  = threadIdx.x;
    int lane = tid & 31;
    int w    = tid >> 5;
    int wm   = w >> 2;
    int wn   = w & 3;
    int t0   = blockIdx.y * 128;
    int v0   = blockIdx.x * 128;

    const __nv_bfloat16* Hbf = g_Hbf;
    const __nv_bfloat16* Wbf = g_Wbf;

    float acc[4][4][4];
    #pragma unroll
    for (int mi = 0; mi < 4; ++mi)
        #pragma unroll
        for (int ni = 0; ni < 4; ++ni)
            #pragma unroll
            for (int q = 0; q < 4; ++q) acc[mi][ni][q] = 0.f;

    #pragma unroll
    for (int s = 0; s < 2; ++s) {
        int f = tid + s * 256, row = f >> 2, q = f & 3;
        *(uint4*)&As[0][row][q * 8] =
            *(const uint4*)(Hbf + (size_t)(t0 + row) * D + q * 8);
        *(uint4*)&Bs[0][row][q * 8] =
            *(const uint4*)(Wbf + (size_t)(v0 + row) * D + q * 8);
    }
    __syncthreads();

    int p = 0;
    for (int kb = 0; kb < 32; ++kb) {
        uint4 ra[2], rb[2];
        if (kb < 31) {
            int d0 = (kb + 1) * 32;
            #pragma unroll
            for (int s = 0; s < 2; ++s) {
                int f = tid + s * 256, row = f >> 2, q = f & 3;
                ra[s] = *(const uint4*)(Hbf + (size_t)(t0 + row) * D + d0 + q * 8);
                rb[s] = *(const uint4*)(Wbf + (size_t)(v0 + row) * D + d0 + q * 8);
            }
        }

        #pragma unroll
        for (int ks = 0; ks < 2; ++ks) {
            int k0 = ks * 16;
            uint32_t af[4][4];
            #pragma unroll
            for (int mi = 0; mi < 4; ++mi) {
                int row = wm * 64 + mi * 16 + (lane & 7) + ((lane >> 3) & 1) * 8;
                int kc  = k0 + (lane >> 4) * 8;
                uint32_t a = (uint32_t)__cvta_generic_to_shared(&As[p][row][kc]);
                asm volatile(
                    "ldmatrix.sync.aligned.m8n8.x4.shared.b16 {%0,%1,%2,%3}, [%4];"
                    : "=r"(af[mi][0]), "=r"(af[mi][1]),
                      "=r"(af[mi][2]), "=r"(af[mi][3]) : "r"(a));
            }
            uint32_t bfr[4][2];
            #pragma unroll
            for (int ni = 0; ni < 4; ++ni) {
                int nrow = wn * 32 + ni * 8 + (lane & 7);
                int kc   = k0 + ((lane >> 3) & 1) * 8;
                uint32_t a = (uint32_t)__cvta_generic_to_shared(&Bs[p][nrow][kc]);
                asm volatile(
                    "ldmatrix.sync.aligned.m8n8.x2.shared.b16 {%0,%1}, [%2];"
                    : "=r"(bfr[ni][0]), "=r"(bfr[ni][1]) : "r"(a));
            }
            #pragma unroll
            for (int mi = 0; mi < 4; ++mi)
                #pragma unroll
                for (int ni = 0; ni < 4; ++ni)
                    asm volatile(
                        "mma.sync.aligned.m16n8k16.row.col.f32.bf16.bf16.f32 "
                        "{%0,%1,%2,%3}, {%4,%5,%6,%7}, {%8,%9}, {%0,%1,%2,%3};"
                        : "+f"(acc[mi][ni][0]), "+f"(acc[mi][ni][1]),
                          "+f"(acc[mi][ni][2]), "+f"(acc[mi][ni][3])
                        : "r"(af[mi][0]), "r"(af[mi][1]),
                          "r"(af[mi][2]), "r"(af[mi][3]),
                          "r"(bfr[ni][0]), "r"(bfr[ni][1]));
        }

        if (kb < 31) {
            #pragma unroll
            for (int s = 0; s < 2; ++s) {
                int f = tid + s * 256, row = f >> 2, q = f & 3;
                *(uint4*)&As[p ^ 1][row][q * 8] = ra[s];
                *(uint4*)&Bs[p ^ 1][row][q * 8] = rb[s];
            }
        }
        __syncthreads();
        p ^= 1;
    }

    int rowA = lane >> 2;
    int colB = (lane & 3) * 2;
    #pragma unroll
    for (int mi = 0; mi < 4; ++mi) {
        int m = t0 + wm * 64 + mi * 16 + rowA;
        #pragma unroll
        for (int ni = 0; ni < 4; ++ni) {
            int n = v0 + wn * 32 + ni * 8 + colB;
            float bx = bias[n], by = bias[n + 1];
            *(float2*)(out + (size_t)m * V + n) =
                make_float2(acc[mi][ni][0] + bx, acc[mi][ni][1] + by);
            *(float2*)(out + (size_t)(m + 8) * V + n) =
                make_float2(acc[mi][ni][2] + bx, acc[mi][ni][3] + by);
        }
    }
}

// ---------------- kernel 4: online single-read log_softmax ----------------
__global__ void __launch_bounds__(256) logsoftmax_kernel(float* __restrict__ out)
{
    size_t t   = blockIdx.x;
    float* row = out + t * (size_t)V;
    int tid = threadIdx.x;
    __shared__ float sm[8], ss[8];

    float m = -INFINITY, s = 0.f;
    const float4* r4 = (const float4*)row;
    for (int i = tid; i < V / 4; i += 256) {
        float4 v = r4[i];
        float mx = fmaxf(fmaxf(v.x, v.y), fmaxf(v.z, v.w));
        if (mx > m) { s *= expf(m - mx); m = mx; }
        s += expf(v.x - m) + expf(v.y - m) + expf(v.z - m) + expf(v.w - m);
    }
    #pragma unroll
    for (int o = 16; o; o >>= 1) {
        float mo = __shfl_xor_sync(0xffffffffu, m, o);
        float so = __shfl_xor_sync(0xffffffffu, s, o);
        float mn = fmaxf(m, mo);
        s = s * expf(m - mn) + so * expf(mo - mn);
        m = mn;
    }
    if ((tid & 31) == 0) { sm[tid >> 5] = m; ss[tid >> 5] = s; }
    __syncthreads();
    float M = sm[0], S = ss[0];
    #pragma unroll
    for (int i = 1; i < 8; ++i) {
        float mo = sm[i], so = ss[i];
        float mn = fmaxf(M, mo);
        S = S * expf(M - mn) + so * expf(mo - mn);
        M = mn;
    }
    float lse = M + logf(S);
    for (int i = tid; i < V / 4; i += 256) {
        float4 v = r4[i];
        v.x -= lse; v.y -= lse; v.z -= lse; v.w -= lse;
        ((float4*)row)[i] = v;
    }
}

// ---------------- launch ----------------
extern "C" void kernel_launch(void* const* d_in, const int* in_sizes, int n_in,
                              void* d_out, int out_size)
{
    const int*   X   = (const int*)d_in[0];
    const float* Wxf = (const float*)d_in[1];
    const float* Whf = (const float*)d_in[2];
    const float* Wxi = (const float*)d_in[3];
    const float* Whi = (const float*)d_in[4];
    const float* Wxc = (const float*)d_in[5];
    const float* Whc = (const float*)d_in[6];
    const float* Wxo = (const float*)d_in[7];
    const float* Who = (const float*)d_in[8];
    const float* LW  = (const float*)d_in[9];
    const float* bf  = (const float*)d_in[10];
    const float* bi  = (const float*)d_in[11];
    const float* bc  = (const float*)d_in[12];
    const float* bo  = (const float*)d_in[13];
    const float* LB  = (const float*)d_in[14];

    float* out = (float*)d_out;                     // (T, V) log-softmax
    float* hid = out + (size_t)T * V;               // (1, T, D) hidden states

    gather_kernel<<<T, 256>>>(X, Wxf, Wxi, Wxc, Wxo, bf, bi, bc, bo);
    cvt_kernel<<<(int)(((size_t)V * D / 4) / 256), 256>>>(LW);
    lstm_kernel<<<NB, 256>>>(Whf, Whi, Whc, Who, hid);
    dim3 gg(V / 128, T / 128);
    gemm_kernel<<<gg, 256>>>(LB, out);
    logsoftmax_kernel<<<T, 256>>>(out);
}

// round 9
// speedup vs baseline: 2.3789x; 1.4506x over previous
#include <cuda_runtime.h>
#include <cuda_bf16.h>
#include <cstdint>
#include <math.h>

#define D  1024
#define T  2048
#define V  32000
#define NB 128     // persistent CTAs, 1 per SM (128 <= 148)
#define JT 8       // hidden units owned per CTA (NB*JT == D)

// ---------------- device scratch (no allocs allowed) ----------------
__device__ __align__(16) float g_xpre[(size_t)T * 4 * D];    // 32 MB x-contrib + bias
// tagged hidden state, double-buffered by step parity: {tag:32 | h_bits:32}
__device__ __align__(16) unsigned long long g_hpk[2][D];
__device__ __align__(16) __nv_bfloat16 g_Hbf[(size_t)T * D]; // 4 MB bf16 hidden states
__device__ __align__(16) __nv_bfloat16 g_Wbf[(size_t)V * D]; // 64 MB bf16 linear weight

// ---------------- kernel 1: gather x-projections, reset state ----------------
__global__ void __launch_bounds__(256) gather_kernel(
    const int* __restrict__ X32,
    const float* __restrict__ Wxf, const float* __restrict__ Wxi,
    const float* __restrict__ Wxc, const float* __restrict__ Wxo,
    const float* __restrict__ bf,  const float* __restrict__ bi,
    const float* __restrict__ bc,  const float* __restrict__ bo)
{
    int t   = blockIdx.x;
    int tid = threadIdx.x;

    // int64 vs int32 ids: little-endian int64 ids < 32000 -> odd words zero.
    int pred = 0;
    if (tid < 64) {
        int p = (tid * 37) & 1023;
        pred = (X32[2 * p + 1] != 0);
    }
    int any_nonzero = __syncthreads_or(pred);
    int id = any_nonzero ? X32[t] : X32[2 * t];

    if (t == 0) {
        // h^0 = 0 with tag 0 in slot 0; slot 1 tag 0 (!= any wanted odd tag)
        #pragma unroll
        for (int q = 0; q < 4; ++q) {
            g_hpk[0][tid * 4 + q] = 0ull;
            g_hpk[1][tid * 4 + q] = 0ull;
        }
    }

    const float* Wx[4] = {Wxf, Wxi, Wxc, Wxo};
    const float* bs[4] = {bf,  bi,  bc,  bo};
    size_t rowoff = (size_t)id * D;
    int j = tid * 4;
    #pragma unroll
    for (int g = 0; g < 4; ++g) {
        float4 v = *(const float4*)(Wx[g] + rowoff + j);
        float4 b = *(const float4*)(bs[g] + j);
        v.x += b.x; v.y += b.y; v.z += b.z; v.w += b.w;
        *(float4*)(g_xpre + ((size_t)t * 4 + g) * D + j) = v;
    }
}

// ---------------- kernel 1b: convert linear_weight to bf16 ----------------
__global__ void __launch_bounds__(256) cvt_kernel(const float* __restrict__ W)
{
    size_t i = (size_t)blockIdx.x * 256 + threadIdx.x;   // float4 index
    float4 v = ((const float4*)W)[i];
    __nv_bfloat162* o = (__nv_bfloat162*)g_Wbf + i * 2;
    o[0] = __floats2bfloat162_rn(v.x, v.y);
    o[1] = __floats2bfloat162_rn(v.z, v.w);
}

// ---------------- kernel 2: persistent LSTM, weights in registers ----------
// 128 CTAs x 256 threads, 1 CTA/SM. Thread (warp w, lane) holds
// W[gate(lane>>3)][k in 128w..128(w+1))][j = 8*cta + (lane&7)] in 128 regs.
// Sync protocol: h values published as tagged 8-byte words {step+1, bits};
// readers volatile-poll their own 4 words. No fences, no atomics, no flags.
__global__ void __launch_bounds__(256, 1) lstm_kernel(
    const float* __restrict__ Whf, const float* __restrict__ Whi,
    const float* __restrict__ Whc, const float* __restrict__ Who,
    float* __restrict__ hid_out)
{
    __shared__ float sh_h[D];
    __shared__ float sh_ps[8][33];

    int tid   = threadIdx.x;
    int w     = tid >> 5;
    int lane  = tid & 31;
    int g     = lane >> 3;
    int jj    = lane & 7;
    int jbase = blockIdx.x * JT;
    int j     = jbase + jj;

    const float* Wm = (g == 0) ? Whf : (g == 1) ? Whi : (g == 2) ? Whc : Who;
    float wreg[128];
    #pragma unroll
    for (int kk = 0; kk < 128; ++kk)
        wreg[kk] = Wm[(size_t)(w * 128 + kk) * D + j];

    float c = 0.f;   // cell state: lives in warp-0 lanes 0..7

    for (int t = 0; t < T; ++t) {
        // x-contribution (DRAM streaming; issued early, consumed after reduce)
        float xv = 0.f;
        if (w == 0) xv = __ldcs(&g_xpre[((size_t)t * 4 + g) * D + j]);

        // acquire h^t: poll own 4 tagged words (volatile -> non-hoistable)
        {
            const volatile unsigned long long* hp = &g_hpk[t & 1][tid * 4];
            unsigned tag = (unsigned)t;
            unsigned long long v0, v1, v2, v3;
            for (;;) {
                v0 = hp[0]; v1 = hp[1]; v2 = hp[2]; v3 = hp[3];
                if ((unsigned)(v0 >> 32) == tag && (unsigned)(v1 >> 32) == tag &&
                    (unsigned)(v2 >> 32) == tag && (unsigned)(v3 >> 32) == tag)
                    break;
            }
            ((float4*)sh_h)[tid] = make_float4(
                __uint_as_float((unsigned)v0), __uint_as_float((unsigned)v1),
                __uint_as_float((unsigned)v2), __uint_as_float((unsigned)v3));
        }
        __syncthreads();   // (A) sh_h complete; also protects sh_ps reuse

        float a0 = 0.f, a1 = 0.f, a2 = 0.f, a3 = 0.f;
        const float4* h4 = ((const float4*)sh_h) + w * 32;
        #pragma unroll
        for (int q = 0; q < 32; ++q) {
            float4 hv = h4[q];
            a0 = fmaf(hv.x, wreg[4 * q + 0], a0);
            a1 = fmaf(hv.y, wreg[4 * q + 1], a1);
            a2 = fmaf(hv.z, wreg[4 * q + 2], a2);
            a3 = fmaf(hv.w, wreg[4 * q + 3], a3);
        }
        sh_ps[w][lane] = (a0 + a1) + (a2 + a3);
        __syncthreads();   // (B) sh_ps complete

        if (w == 0) {
            float s = xv;
            #pragma unroll
            for (int q = 0; q < 8; ++q) s += sh_ps[q][lane];
            float a = (g == 2) ? tanhf(s) : 1.f / (1.f + expf(-s));
            float fv = __shfl_sync(0xffffffffu, a, jj);
            float iv = __shfl_sync(0xffffffffu, a, 8 + jj);
            float gv = __shfl_sync(0xffffffffu, a, 16 + jj);
            float ov = __shfl_sync(0xffffffffu, a, 24 + jj);
            if (lane < 8) {
                c = fmaf(fv, c, iv * gv);
                float h = tanhf(c) * ov;
                // publish FIRST: single aligned 8B store = atomic, self-flagging
                unsigned long long pk =
                    ((unsigned long long)(unsigned)(t + 1) << 32) |
                    (unsigned long long)__float_as_uint(h);
                *(volatile unsigned long long*)&g_hpk[(t + 1) & 1][jbase + lane] = pk;
                // off critical path:
                hid_out[(size_t)t * D + jbase + lane] = h;
                g_Hbf[(size_t)t * D + jbase + lane] = __float2bfloat16(h);
            }
        }
        // no trailing sync needed: next poll writes sh_h (all reads done at B),
        // sh_ps writes of t+1 are gated by sync (A) which warp 0 joins too.
    }
}

// ---------------- kernel 3: bf16 tensor-core GEMM  C = H @ W^T + bias ----------
// 128x128 block tile, BK=32, 8 warps (2x4), 64x32 warp tile, mma.m16n8k16.bf16.
__global__ void __launch_bounds__(256) gemm_kernel(
    const float* __restrict__ bias,   // (V)
    float* __restrict__ out)          // (T, V)
{
    __shared__ __align__(16) __nv_bfloat16 As[2][128][40];
    __shared__ __align__(16) __nv_bfloat16 Bs[2][128][40];

    int tid  = threadIdx.x;
    int lane = tid & 31;
    int w    = tid >> 5;
    int wm   = w >> 2;
    int wn   = w & 3;
    int t0   = blockIdx.y * 128;
    int v0   = blockIdx.x * 128;

    const __nv_bfloat16* Hbf = g_Hbf;
    const __nv_bfloat16* Wbf = g_Wbf;

    float acc[4][4][4];
    #pragma unroll
    for (int mi = 0; mi < 4; ++mi)
        #pragma unroll
        for (int ni = 0; ni < 4; ++ni)
            #pragma unroll
            for (int q = 0; q < 4; ++q) acc[mi][ni][q] = 0.f;

    #pragma unroll
    for (int s = 0; s < 2; ++s) {
        int f = tid + s * 256, row = f >> 2, q = f & 3;
        *(uint4*)&As[0][row][q * 8] =
            *(const uint4*)(Hbf + (size_t)(t0 + row) * D + q * 8);
        *(uint4*)&Bs[0][row][q * 8] =
            *(const uint4*)(Wbf + (size_t)(v0 + row) * D + q * 8);
    }
    __syncthreads();

    int p = 0;
    for (int kb = 0; kb < 32; ++kb) {
        uint4 ra[2], rb[2];
        if (kb < 31) {
            int d0 = (kb + 1) * 32;
            #pragma unroll
            for (int s = 0; s < 2; ++s) {
                int f = tid + s * 256, row = f >> 2, q = f & 3;
                ra[s] = *(const uint4*)(Hbf + (size_t)(t0 + row) * D + d0 + q * 8);
                rb[s] = *(const uint4*)(Wbf + (size_t)(v0 + row) * D + d0 + q * 8);
            }
        }

        #pragma unroll
        for (int ks = 0; ks < 2; ++ks) {
            int k0 = ks * 16;
            uint32_t af[4][4];
            #pragma unroll
            for (int mi = 0; mi < 4; ++mi) {
                int row = wm * 64 + mi * 16 + (lane & 7) + ((lane >> 3) & 1) * 8;
                int kc  = k0 + (lane >> 4) * 8;
                uint32_t a = (uint32_t)__cvta_generic_to_shared(&As[p][row][kc]);
                asm volatile(
                    "ldmatrix.sync.aligned.m8n8.x4.shared.b16 {%0,%1,%2,%3}, [%4];"
                    : "=r"(af[mi][0]), "=r"(af[mi][1]),
                      "=r"(af[mi][2]), "=r"(af[mi][3]) : "r"(a));
            }
            uint32_t bfr[4][2];
            #pragma unroll
            for (int ni = 0; ni < 4; ++ni) {
                int nrow = wn * 32 + ni * 8 + (lane & 7);
                int kc   = k0 + ((lane >> 3) & 1) * 8;
                uint32_t a = (uint32_t)__cvta_generic_to_shared(&Bs[p][nrow][kc]);
                asm volatile(
                    "ldmatrix.sync.aligned.m8n8.x2.shared.b16 {%0,%1}, [%2];"
                    : "=r"(bfr[ni][0]), "=r"(bfr[ni][1]) : "r"(a));
            }
            #pragma unroll
            for (int mi = 0; mi < 4; ++mi)
                #pragma unroll
                for (int ni = 0; ni < 4; ++ni)
                    asm volatile(
                        "mma.sync.aligned.m16n8k16.row.col.f32.bf16.bf16.f32 "
                        "{%0,%1,%2,%3}, {%4,%5,%6,%7}, {%8,%9}, {%0,%1,%2,%3};"
                        : "+f"(acc[mi][ni][0]), "+f"(acc[mi][ni][1]),
                          "+f"(acc[mi][ni][2]), "+f"(acc[mi][ni][3])
                        : "r"(af[mi][0]), "r"(af[mi][1]),
                          "r"(af[mi][2]), "r"(af[mi][3]),
                          "r"(bfr[ni][0]), "r"(bfr[ni][1]));
        }

        if (kb < 31) {
            #pragma unroll
            for (int s = 0; s < 2; ++s) {
                int f = tid + s * 256, row = f >> 2, q = f & 3;
                *(uint4*)&As[p ^ 1][row][q * 8] = ra[s];
                *(uint4*)&Bs[p ^ 1][row][q * 8] = rb[s];
            }
        }
        __syncthreads();
        p ^= 1;
    }

    int rowA = lane >> 2;
    int colB = (lane & 3) * 2;
    #pragma unroll
    for (int mi = 0; mi < 4; ++mi) {
        int m = t0 + wm * 64 + mi * 16 + rowA;
        #pragma unroll
        for (int ni = 0; ni < 4; ++ni) {
            int n = v0 + wn * 32 + ni * 8 + colB;
            float bx = bias[n], by = bias[n + 1];
            *(float2*)(out + (size_t)m * V + n) =
                make_float2(acc[mi][ni][0] + bx, acc[mi][ni][1] + by);
            *(float2*)(out + (size_t)(m + 8) * V + n) =
                make_float2(acc[mi][ni][2] + bx, acc[mi][ni][3] + by);
        }
    }
}

// ---------------- kernel 4: online single-read log_softmax ----------------
__global__ void __launch_bounds__(256) logsoftmax_kernel(float* __restrict__ out)
{
    size_t t   = blockIdx.x;
    float* row = out + t * (size_t)V;
    int tid = threadIdx.x;
    __shared__ float sm[8], ss[8];

    float m = -INFINITY, s = 0.f;
    const float4* r4 = (const float4*)row;
    for (int i = tid; i < V / 4; i += 256) {
        float4 v = r4[i];
        float mx = fmaxf(fmaxf(v.x, v.y), fmaxf(v.z, v.w));
        if (mx > m) { s *= expf(m - mx); m = mx; }
        s += expf(v.x - m) + expf(v.y - m) + expf(v.z - m) + expf(v.w - m);
    }
    #pragma unroll
    for (int o = 16; o; o >>= 1) {
        float mo = __shfl_xor_sync(0xffffffffu, m, o);
        float so = __shfl_xor_sync(0xffffffffu, s, o);
        float mn = fmaxf(m, mo);
        s = s * expf(m - mn) + so * expf(mo - mn);
        m = mn;
    }
    if ((tid & 31) == 0) { sm[tid >> 5] = m; ss[tid >> 5] = s; }
    __syncthreads();
    float M = sm[0], S = ss[0];
    #pragma unroll
    for (int i = 1; i < 8; ++i) {
        float mo = sm[i], so = ss[i];
        float mn = fmaxf(M, mo);
        S = S * expf(M - mn) + so * expf(mo - mn);
        M = mn;
    }
    float lse = M + logf(S);
    for (int i = tid; i < V / 4; i += 256) {
        float4 v = r4[i];
        v.x -= lse; v.y -= lse; v.z -= lse; v.w -= lse;
        ((float4*)row)[i] = v;
    }
}

// ---------------- launch ----------------
extern "C" void kernel_launch(void* const* d_in, const int* in_sizes, int n_in,
                              void* d_out, int out_size)
{
    const int*   X   = (const int*)d_in[0];
    const float* Wxf = (const float*)d_in[1];
    const float* Whf = (const float*)d_in[2];
    const float* Wxi = (const float*)d_in[3];
    const float* Whi = (const float*)d_in[4];
    const float* Wxc = (const float*)d_in[5];
    const float* Whc = (const float*)d_in[6];
    const float* Wxo = (const float*)d_in[7];
    const float* Who = (const float*)d_in[8];
    const float* LW  = (const float*)d_in[9];
    const float* bf  = (const float*)d_in[10];
    const float* bi  = (const float*)d_in[11];
    const float* bc  = (const float*)d_in[12];
    const float* bo  = (const float*)d_in[13];
    const float* LB  = (const float*)d_in[14];

    float* out = (float*)d_out;                     // (T, V) log-softmax
    float* hid = out + (size_t)T * V;               // (1, T, D) hidden states

    gather_kernel<<<T, 256>>>(X, Wxf, Wxi, Wxc, Wxo, bf, bi, bc, bo);
    cvt_kernel<<<(int)(((size_t)V * D / 4) / 256), 256>>>(LW);
    lstm_kernel<<<NB, 256>>>(Whf, Whi, Whc, Who, hid);
    dim3 gg(V / 128, T / 128);
    gemm_kernel<<<gg, 256>>>(LB, out);
    logsoftmax_kernel<<<T, 256>>>(out);
}